// round 16
// baseline (speedup 1.0000x reference)
#include <cuda_runtime.h>

#define C_   16
#define GX_  36
#define GY_  36
#define RF_  24
#define IMG_ 64
#define G_   (GX_ * GY_)        // 1296
#define GAMMA_E 0.9f
#define GAMMA_I 0.9f

// Combined partial per (ij,c): aff + ge*p*exc - gi*p*inh.
// Layout [ij][c]: each ij's 16 partials are one contiguous 64B span.
__device__ float g_part[G_ * C_];

__global__ __launch_bounds__(128, 16)
void cortex_partial(const float* __restrict__ x,
                    const float* __restrict__ prev,
                    const float* __restrict__ aw,
                    const float* __restrict__ ew,
                    const float* __restrict__ iw,
                    const int*   __restrict__ rx,
                    const int*   __restrict__ ry)
{
    const int ij = blockIdx.x;           // 0..1295
    const int c  = blockIdx.y;           // 0..15
    const int i  = ij / GY_;
    const int j  = ij - i * GY_;
    const int t  = threadIdx.x;

    // ---- Front-batched scalar chain loads ----
    const int rxi = __ldg(rx + i), ryj = __ldg(ry + j);
    const float p0 = (t == 0) ? __ldg(prev + c * G_ + ij) : 0.f;

    // ---- Explicit front-batched weight loads ----
    // Lateral: 324 f4 per tensor over 128 threads -> o = t, t+128 (uncond),
    // t+256 (pred t<68). Afferent: 144 f4 -> o = t (uncond), t+128 (pred t<16).
    const size_t rowbase = (size_t)(c * G_ + ij) * G_;
    const float4* e4 = reinterpret_cast<const float4*>(ew + rowbase);
    const float4* i4 = reinterpret_cast<const float4*>(iw + rowbase);
    const float4* a4 = reinterpret_cast<const float4*>(
        aw + (size_t)(c * G_ + ij) * (RF_ * RF_));

    const bool pl = t < (324 - 256);     // t < 68
    const bool pa = t < (144 - 128);     // t < 16

    const float4 w40 = __ldcs(a4 + t);
    const float4 ve0 = __ldcs(e4 + t);
    const float4 vi0 = __ldcs(i4 + t);
    const float4 ve1 = __ldcs(e4 + t + 128);
    const float4 vi1 = __ldcs(i4 + t + 128);
    float4 w41 = make_float4(0.f, 0.f, 0.f, 0.f);
    float4 ve2 = make_float4(0.f, 0.f, 0.f, 0.f);
    float4 vi2 = make_float4(0.f, 0.f, 0.f, 0.f);
    if (pa) w41 = __ldcs(a4 + t + 128);
    if (pl) { ve2 = __ldcs(e4 + t + 256); vi2 = __ldcs(i4 + t + 256); }

    // ---- Afferent x gathers (addresses ready once rx/ry returned) ----
    float aff;
    {
        const int uv0 = t * 4;
        const int u0  = uv0 / RF_;
        const int v0  = uv0 - u0 * RF_;
        const float* xr0 = x + c * IMG_ * IMG_ + (rxi + u0) * IMG_ + (ryj + v0);
        aff = w40.x * __ldg(xr0 + 0) + w40.y * __ldg(xr0 + 1)
            + w40.z * __ldg(xr0 + 2) + w40.w * __ldg(xr0 + 3);
        if (pa) {
            const int uv1 = (t + 128) * 4;
            const int u1  = uv1 / RF_;
            const int v1  = uv1 - u1 * RF_;
            const float* xr1 = x + c * IMG_ * IMG_ + (rxi + u1) * IMG_ + (ryj + v1);
            aff += w41.x * __ldg(xr1 + 0) + w41.y * __ldg(xr1 + 1)
                 + w41.z * __ldg(xr1 + 2) + w41.w * __ldg(xr1 + 3);
        }
    }

    // ---- Lateral sums from the batched registers ----
    const float se = ((ve0.x + ve0.y) + (ve0.z + ve0.w))
                   + ((ve1.x + ve1.y) + (ve1.z + ve1.w))
                   + ((ve2.x + ve2.y) + (ve2.z + ve2.w));
    const float si = ((vi0.x + vi0.y) + (vi0.z + vi0.w))
                   + ((vi1.x + vi1.y) + (vi1.z + vi1.w))
                   + ((vi2.x + vi2.y) + (vi2.z + vi2.w));

    // ---- Block reduce (128 threads = 4 warps) ----
    float raff = aff, rse = se, rsi = si;
    const unsigned FULL = 0xFFFFFFFFu;
    #pragma unroll
    for (int off = 16; off > 0; off >>= 1) {
        raff += __shfl_down_sync(FULL, raff, off);
        rse  += __shfl_down_sync(FULL, rse,  off);
        rsi  += __shfl_down_sync(FULL, rsi,  off);
    }
    __shared__ float s_red[3][4];
    const int wid = t >> 5, lid = t & 31;
    if (lid == 0) { s_red[0][wid] = raff; s_red[1][wid] = rse; s_red[2][wid] = rsi; }
    __syncthreads();

    if (t == 0) {
        const float a = s_red[0][0] + s_red[0][1] + s_red[0][2] + s_red[0][3];
        const float e = s_red[1][0] + s_red[1][1] + s_red[1][2] + s_red[1][3];
        const float v = s_red[2][0] + s_red[2][1] + s_red[2][2] + s_red[2][3];
        g_part[ij * C_ + c] = a + GAMMA_E * (p0 * e) - GAMMA_I * (p0 * v);
    }

    // Allow the dependent (finalize) grid to start (R6-proven placement).
    asm volatile("griddepcontrol.launch_dependents;");
}

// One warp per ij: coalesced 64B load of the 16 partials, shuffle reduce,
// relu, broadcast-store to the 16 output channels (R6's proven finalize).
__global__ __launch_bounds__(256)
void cortex_finalize(float* __restrict__ out)
{
    const int gw   = (blockIdx.x * blockDim.x + threadIdx.x) >> 5;  // warp id
    const int lane = threadIdx.x & 31;

    // Wait until all memory from cortex_partial is visible.
    asm volatile("griddepcontrol.wait;" ::: "memory");

    if (gw >= G_) return;

    float v = (lane < C_) ? g_part[gw * C_ + lane] : 0.f;
    const unsigned FULL = 0xFFFFFFFFu;
    v += __shfl_down_sync(FULL, v, 8);
    v += __shfl_down_sync(FULL, v, 4);
    v += __shfl_down_sync(FULL, v, 2);
    v += __shfl_down_sync(FULL, v, 1);
    const float act = fmaxf(__shfl_sync(FULL, v, 0), 0.f);
    if (lane < C_)
        out[lane * G_ + gw] = act;
}

extern "C" void kernel_launch(void* const* d_in, const int* in_sizes, int n_in,
                              void* d_out, int out_size)
{
    const float* x    = (const float*)d_in[0];
    const float* prev = (const float*)d_in[1];
    const float* aw   = (const float*)d_in[2];
    const float* ew   = (const float*)d_in[3];
    const float* iw   = (const float*)d_in[4];
    const int*   rx   = (const int*)d_in[5];
    const int*   ry   = (const int*)d_in[6];
    float* out = (float*)d_out;

    dim3 grid(G_, C_);
    cortex_partial<<<grid, 128>>>(x, prev, aw, ew, iw, rx, ry);

    // Finalize with PDL (overlaps the partial's tail). 162 CTAs, warp per ij.
    const int warps_per_cta = 256 / 32;
    const int n_cta = (G_ + warps_per_cta - 1) / warps_per_cta;   // 162

    cudaLaunchConfig_t cfg = {};
    cfg.gridDim  = dim3(n_cta, 1, 1);
    cfg.blockDim = dim3(256, 1, 1);
    cfg.dynamicSmemBytes = 0;
    cudaLaunchAttribute attrs[1];
    attrs[0].id = cudaLaunchAttributeProgrammaticStreamSerialization;
    attrs[0].val.programmaticStreamSerializationAllowed = 1;
    cfg.attrs = attrs;
    cfg.numAttrs = 1;
    cudaLaunchKernelEx(&cfg, cortex_finalize, out);
}

// round 17
// speedup vs baseline: 1.2179x; 1.2179x over previous
#include <cuda_runtime.h>

#define C_   16
#define GX_  36
#define GY_  36
#define RF_  24
#define IMG_ 64
#define G_   (GX_ * GY_)        // 1296
#define GAMMA_E 0.9f
#define GAMMA_I 0.9f

// Combined partial per (ij,c): aff + ge*p*exc - gi*p*inh.
// Layout [ij][c]: each ij's 16 partials are one contiguous 64B span.
__device__ float g_part[G_ * C_];

__global__ __launch_bounds__(128, 16)
void cortex_partial(const float* __restrict__ x,
                    const float* __restrict__ prev,
                    const float* __restrict__ aw,
                    const float* __restrict__ ew,
                    const float* __restrict__ iw,
                    const int*   __restrict__ rx,
                    const int*   __restrict__ ry)
{
    const int ij = blockIdx.x;           // 0..1295
    const int c  = blockIdx.y;           // 0..15
    const int i  = ij / GY_;
    const int j  = ij - i * GY_;
    const int t  = threadIdx.x;

    // Hoisted scalar loads: rx/ry feed the afferent address chain; prev is
    // needed by thread 0 after the reduce (was a serial L2 access there).
    const int rxi = __ldg(rx + i), ryj = __ldg(ry + j);
    const float p0 = (t == 0) ? __ldg(prev + c * G_ + ij) : 0.f;

    // ---- Afferent FIRST (longest dependent chain: rx/ry -> addr -> x) ----
    // Issuing it up front lets its latency hide under the lateral stream.
    float aff = 0.f;
    const float4* a4 = reinterpret_cast<const float4*>(
        aw + (size_t)(c * G_ + ij) * (RF_ * RF_));
    #pragma unroll
    for (int o = t; o < (RF_ * RF_) / 4; o += 128) {   // 144 f4: 1-2 iters
        const float4 w4 = __ldcs(a4 + o);
        const int uv = o * 4;
        const int u  = uv / RF_;
        const int v  = uv - u * RF_;
        const float* xr = x + c * IMG_ * IMG_ + (rxi + u) * IMG_ + (ryj + v);
        aff += w4.x * __ldg(xr + 0) + w4.y * __ldg(xr + 1)
             + w4.z * __ldg(xr + 2) + w4.w * __ldg(xr + 3);
    }

    // ---- Lateral row sums (324 float4 per tensor, streamed once) ----
    const size_t rowbase = (size_t)(c * G_ + ij) * G_;
    const float4* e4 = reinterpret_cast<const float4*>(ew + rowbase);
    const float4* i4 = reinterpret_cast<const float4*>(iw + rowbase);
    float se = 0.f, si = 0.f;
    const int NF4 = G_ / 4;              // 324
    #pragma unroll
    for (int o = t; o < NF4; o += 128) {
        const float4 ve = __ldcs(e4 + o);
        const float4 vi = __ldcs(i4 + o);
        se += (ve.x + ve.y) + (ve.z + ve.w);
        si += (vi.x + vi.y) + (vi.z + vi.w);
    }

    // ---- Block reduce (128 threads = 4 warps) ----
    const unsigned FULL = 0xFFFFFFFFu;
    #pragma unroll
    for (int off = 16; off > 0; off >>= 1) {
        aff += __shfl_down_sync(FULL, aff, off);
        se  += __shfl_down_sync(FULL, se,  off);
        si  += __shfl_down_sync(FULL, si,  off);
    }
    __shared__ float s_red[3][4];
    const int wid = t >> 5, lid = t & 31;
    if (lid == 0) { s_red[0][wid] = aff; s_red[1][wid] = se; s_red[2][wid] = si; }
    __syncthreads();

    if (t == 0) {
        const float a = s_red[0][0] + s_red[0][1] + s_red[0][2] + s_red[0][3];
        const float e = s_red[1][0] + s_red[1][1] + s_red[1][2] + s_red[1][3];
        const float v = s_red[2][0] + s_red[2][1] + s_red[2][2] + s_red[2][3];
        g_part[ij * C_ + c] = a + GAMMA_E * (p0 * e) - GAMMA_I * (p0 * v);
    }

    // Allow the dependent (finalize) grid to start (R6-proven placement).
    asm volatile("griddepcontrol.launch_dependents;");
}

// One warp per ij: coalesced 64B load of the 16 partials, shuffle reduce,
// relu, broadcast-store to the 16 output channels (R6's proven finalize).
__global__ __launch_bounds__(256)
void cortex_finalize(float* __restrict__ out)
{
    const int gw   = (blockIdx.x * blockDim.x + threadIdx.x) >> 5;  // warp id
    const int lane = threadIdx.x & 31;

    // Wait until all memory from cortex_partial is visible.
    asm volatile("griddepcontrol.wait;" ::: "memory");

    if (gw >= G_) return;

    float v = (lane < C_) ? g_part[gw * C_ + lane] : 0.f;
    const unsigned FULL = 0xFFFFFFFFu;
    v += __shfl_down_sync(FULL, v, 8);
    v += __shfl_down_sync(FULL, v, 4);
    v += __shfl_down_sync(FULL, v, 2);
    v += __shfl_down_sync(FULL, v, 1);
    const float act = fmaxf(__shfl_sync(FULL, v, 0), 0.f);
    if (lane < C_)
        out[lane * G_ + gw] = act;
}

extern "C" void kernel_launch(void* const* d_in, const int* in_sizes, int n_in,
                              void* d_out, int out_size)
{
    const float* x    = (const float*)d_in[0];
    const float* prev = (const float*)d_in[1];
    const float* aw   = (const float*)d_in[2];
    const float* ew   = (const float*)d_in[3];
    const float* iw   = (const float*)d_in[4];
    const int*   rx   = (const int*)d_in[5];
    const int*   ry   = (const int*)d_in[6];
    float* out = (float*)d_out;

    dim3 grid(G_, C_);
    cortex_partial<<<grid, 128>>>(x, prev, aw, ew, iw, rx, ry);

    // Finalize with PDL (overlaps the partial's tail). 162 CTAs, warp per ij.
    const int warps_per_cta = 256 / 32;
    const int n_cta = (G_ + warps_per_cta - 1) / warps_per_cta;   // 162

    cudaLaunchConfig_t cfg = {};
    cfg.gridDim  = dim3(n_cta, 1, 1);
    cfg.blockDim = dim3(256, 1, 1);
    cfg.dynamicSmemBytes = 0;
    cudaLaunchAttribute attrs[1];
    attrs[0].id = cudaLaunchAttributeProgrammaticStreamSerialization;
    attrs[0].val.programmaticStreamSerializationAllowed = 1;
    cfg.attrs = attrs;
    cfg.numAttrs = 1;
    cudaLaunchKernelEx(&cfg, cortex_finalize, out);
}